// round 1
// baseline (speedup 1.0000x reference)
#include <cuda_runtime.h>
#include <cstdint>

// ---------------------------------------------------------------------------
// Problem constants (B=2, S=2048, H=1024, NH=16, NKV=8, D=128)
// ---------------------------------------------------------------------------
constexpr int B_   = 2;
constexpr int S_   = 2048;
constexpr int H_   = 1024;
constexpr int NH_  = 16;
constexpr int NKV_ = 8;
constexpr int D_   = 128;
constexpr int TOK  = B_ * S_;            // 4096 tokens

// Scratch (device globals; no allocation allowed)
__device__ float g_q [TOK * NH_  * D_];  // 4096 x 2048
__device__ float g_k [TOK * NKV_ * D_];  // 4096 x 1024
__device__ float g_v [TOK * NKV_ * D_];  // 4096 x 1024
__device__ float g_ao[TOK * NH_  * D_];  // 4096 x 2048 (attention output, token-major)

#define DEV_INLINE __device__ __forceinline__

// ---------------------------------------------------------------------------
// Packed f32x2 helpers (Blackwell FFMA2: only reachable via PTX fma.rn.f32x2)
// ---------------------------------------------------------------------------
DEV_INLINE unsigned long long pack2(float lo, float hi) {
    unsigned long long r;
    asm("mov.b64 %0, {%1, %2};"
        : "=l"(r) : "r"(__float_as_uint(lo)), "r"(__float_as_uint(hi)));
    return r;
}
DEV_INLINE unsigned long long fma2(unsigned long long a, unsigned long long b,
                                   unsigned long long c) {
    unsigned long long d;
    asm("fma.rn.f32x2 %0, %1, %2, %3;" : "=l"(d) : "l"(a), "l"(b), "l"(c));
    return d;
}
DEV_INLINE unsigned long long mul2(unsigned long long a, unsigned long long b) {
    unsigned long long d;
    asm("mul.rn.f32x2 %0, %1, %2;" : "=l"(d) : "l"(a), "l"(b));
    return d;
}
DEV_INLINE float2 unpack2(unsigned long long v) {
    unsigned int lo, hi;
    asm("mov.b64 {%0, %1}, %2;" : "=r"(lo), "=r"(hi) : "l"(v));
    return make_float2(__uint_as_float(lo), __uint_as_float(hi));
}

// ---------------------------------------------------------------------------
// NT GEMM: C[m,n] = sum_k A[m,k] * B[n,k]   (A: MxK row-major, B: NxK row-major)
// BM=BN=128, BK=32, 256 threads, 8x8 microtile per thread, f32x2 accumulation,
// register prefetch double-buffering. M,N multiples of 128; K multiple of 32.
// ---------------------------------------------------------------------------
__launch_bounds__(256, 2)
__global__ void gemm_nt_128(const float* __restrict__ A,
                            const float* __restrict__ Bm,
                            float* __restrict__ C,
                            int M, int N, int K)
{
    constexpr int BM = 128, BN = 128, BK = 32;
    __shared__ float As[BK][BM + 4];   // [k][m], stride 132 floats (16B aligned rows)
    __shared__ float Bs[BK][BN + 4];

    const int tid = threadIdx.x;
    const int ty = tid >> 4;           // 0..15 -> row group
    const int tx = tid & 15;           // 0..15 -> col group
    const int m0 = blockIdx.y * BM;
    const int n0 = blockIdx.x * BN;

    unsigned long long acc[8][4];
#pragma unroll
    for (int i = 0; i < 8; i++)
#pragma unroll
        for (int j = 0; j < 4; j++) acc[i][j] = 0ull;

    float4 ra[4], rb[4];

    // prefetch tile 0
#pragma unroll
    for (int rep = 0; rep < 4; rep++) {
        int f = tid + rep * 256;       // float4 id within 128x32 tile
        int row = f >> 3;              // 8 float4 per row
        int kq = f & 7;
        ra[rep] = *reinterpret_cast<const float4*>(A  + (size_t)(m0 + row) * K + kq * 4);
        rb[rep] = *reinterpret_cast<const float4*>(Bm + (size_t)(n0 + row) * K + kq * 4);
    }

    const int ntiles = K / BK;
    for (int t = 0; t < ntiles; t++) {
        // store prefetched tile to smem (transposed: [k][m])
#pragma unroll
        for (int rep = 0; rep < 4; rep++) {
            int f = tid + rep * 256;
            int row = f >> 3;
            int kq = f & 7;
            As[kq * 4 + 0][row] = ra[rep].x;
            As[kq * 4 + 1][row] = ra[rep].y;
            As[kq * 4 + 2][row] = ra[rep].z;
            As[kq * 4 + 3][row] = ra[rep].w;
            Bs[kq * 4 + 0][row] = rb[rep].x;
            Bs[kq * 4 + 1][row] = rb[rep].y;
            Bs[kq * 4 + 2][row] = rb[rep].z;
            Bs[kq * 4 + 3][row] = rb[rep].w;
        }
        __syncthreads();

        // prefetch next tile into registers (overlaps with compute)
        if (t + 1 < ntiles) {
            const int k0 = (t + 1) * BK;
#pragma unroll
            for (int rep = 0; rep < 4; rep++) {
                int f = tid + rep * 256;
                int row = f >> 3;
                int kq = f & 7;
                ra[rep] = *reinterpret_cast<const float4*>(A  + (size_t)(m0 + row) * K + k0 + kq * 4);
                rb[rep] = *reinterpret_cast<const float4*>(Bm + (size_t)(n0 + row) * K + k0 + kq * 4);
            }
        }

#pragma unroll 8
        for (int kk = 0; kk < BK; kk++) {
            float4 a0 = *reinterpret_cast<const float4*>(&As[kk][ty * 8]);
            float4 a1 = *reinterpret_cast<const float4*>(&As[kk][ty * 8 + 4]);
            float4 b0 = *reinterpret_cast<const float4*>(&Bs[kk][tx * 8]);
            float4 b1 = *reinterpret_cast<const float4*>(&Bs[kk][tx * 8 + 4]);
            unsigned long long b2[4];
            b2[0] = pack2(b0.x, b0.y);
            b2[1] = pack2(b0.z, b0.w);
            b2[2] = pack2(b1.x, b1.y);
            b2[3] = pack2(b1.z, b1.w);
            float av[8] = {a0.x, a0.y, a0.z, a0.w, a1.x, a1.y, a1.z, a1.w};
#pragma unroll
            for (int i = 0; i < 8; i++) {
                unsigned long long a2 = pack2(av[i], av[i]);
#pragma unroll
                for (int j = 0; j < 4; j++) acc[i][j] = fma2(a2, b2[j], acc[i][j]);
            }
        }
        __syncthreads();
    }

    // epilogue: coalesced float4 stores
#pragma unroll
    for (int i = 0; i < 8; i++) {
        float2 c0 = unpack2(acc[i][0]);
        float2 c1 = unpack2(acc[i][1]);
        float2 c2 = unpack2(acc[i][2]);
        float2 c3 = unpack2(acc[i][3]);
        size_t base = (size_t)(m0 + ty * 8 + i) * N + n0 + tx * 8;
        *reinterpret_cast<float4*>(&C[base])     = make_float4(c0.x, c0.y, c1.x, c1.y);
        *reinterpret_cast<float4*>(&C[base + 4]) = make_float4(c2.x, c2.y, c3.x, c3.y);
    }
}

// ---------------------------------------------------------------------------
// Fused per-head RMSNorm + RoPE, in place on q / k (token-major layouts).
// grid: (TOK, NH+NKV), block: 128 threads (one per D element)
// ---------------------------------------------------------------------------
__global__ void rmsnorm_rope_kernel(float* __restrict__ qbuf, float* __restrict__ kbuf,
                                    const float* __restrict__ cosb,
                                    const float* __restrict__ sinb,
                                    const float* __restrict__ qw,
                                    const float* __restrict__ kw)
{
    const int t  = blockIdx.x;         // token = b*S + s
    const int hh = blockIdx.y;         // head slot: [0,NH) -> q, [NH,NH+NKV) -> k
    const int d  = threadIdx.x;        // 0..127

    float* ptr;
    const float* w;
    if (hh < NH_) { ptr = qbuf + (size_t)t * (NH_ * D_)  + hh * D_;         w = qw; }
    else          { ptr = kbuf + (size_t)t * (NKV_ * D_) + (hh - NH_) * D_; w = kw; }

    const float x  = ptr[d];
    const float xp = ptr[d ^ 64];      // rotate_half partner

    // mean of squares over 128 elems
    float ss = x * x;
#pragma unroll
    for (int off = 16; off >= 1; off >>= 1) ss += __shfl_xor_sync(0xffffffffu, ss, off);
    __shared__ float red[4];
    if ((d & 31) == 0) red[d >> 5] = ss;
    __syncthreads();   // also orders all loads of ptr[] before the writes below

    const float var = (red[0] + red[1] + red[2] + red[3]) * (1.0f / 128.0f);
    const float inv = rsqrtf(var + 1e-6f);

    const float xn  = x  * inv * w[d];
    const float xpn = xp * inv * w[d ^ 64];
    const float c = cosb[(size_t)t * D_ + d];
    const float s = sinb[(size_t)t * D_ + d];
    const float rot = (d < 64) ? -xpn : xpn;

    ptr[d] = xn * c + rot * s;
}

// ---------------------------------------------------------------------------
// Flash attention (fp32, causal, GQA n_rep=2).
// grid: (S/64, NH, B), 256 threads. BQ=BKV=64, D=128.
// Thread map: ty=tid/16 rows {ty+16i}, S-cols {tx+16j}, O-cols {tx*8+j}.
// ---------------------------------------------------------------------------
constexpr int ATTN_SMEM = (3 * 64 * 132 + 64 * 68) * 4;   // 118784 bytes

__launch_bounds__(256, 1)
__global__ void attn_kernel(const float* __restrict__ q,
                            const float* __restrict__ k,
                            const float* __restrict__ v,
                            float* __restrict__ ao)
{
    extern __shared__ float sm[];
    float* Qs = sm;                   // [64][132]
    float* Ks = Qs + 64 * 132;        // [64][132]
    float* Vs = Ks + 64 * 132;        // [64][132]
    float* Ps = Vs + 64 * 132;        // [64][68]

    const int tid = threadIdx.x;
    const int ty = tid >> 4;
    const int tx = tid & 15;
    const int qi = gridDim.x - 1 - blockIdx.x;   // heavy blocks first
    const int h  = blockIdx.y;
    const int b  = blockIdx.z;
    const int kvh = h >> 1;                      // GQA: 2 q-heads per kv head

    // load Q tile (64 rows x 128)
#pragma unroll
    for (int rep = 0; rep < 8; rep++) {
        int f = tid + rep * 256;
        int row = f >> 5, c4 = f & 31;
        float4 val = *reinterpret_cast<const float4*>(
            q + ((size_t)(b * S_) + qi * 64 + row) * (NH_ * D_) + h * D_ + c4 * 4);
        *reinterpret_cast<float4*>(&Qs[row * 132 + c4 * 4]) = val;
    }

    float m_i[4], l_i[4];
    unsigned long long o2[4][4];
#pragma unroll
    for (int i = 0; i < 4; i++) {
        m_i[i] = -1e30f; l_i[i] = 0.f;
#pragma unroll
        for (int j = 0; j < 4; j++) o2[i][j] = 0ull;
    }

    for (int jb = 0; jb <= qi; jb++) {
        __syncthreads();   // protect smem reuse (and Qs visibility on iter 0)

        // load K/V tiles
#pragma unroll
        for (int rep = 0; rep < 8; rep++) {
            int f = tid + rep * 256;
            int row = f >> 5, c4 = f & 31;
            size_t gidx = ((size_t)(b * S_) + jb * 64 + row) * (NKV_ * D_) + kvh * D_ + c4 * 4;
            *reinterpret_cast<float4*>(&Ks[row * 132 + c4 * 4]) =
                *reinterpret_cast<const float4*>(k + gidx);
            *reinterpret_cast<float4*>(&Vs[row * 132 + c4 * 4]) =
                *reinterpret_cast<const float4*>(v + gidx);
        }
        __syncthreads();

        // S = Q K^T (4x4 microtile, float4 dot along D)
        float acc[4][4];
#pragma unroll
        for (int i = 0; i < 4; i++)
#pragma unroll
            for (int j = 0; j < 4; j++) acc[i][j] = 0.f;

#pragma unroll 4
        for (int kd = 0; kd < D_; kd += 4) {
            float4 a4[4], b4[4];
#pragma unroll
            for (int i = 0; i < 4; i++)
                a4[i] = *reinterpret_cast<const float4*>(&Qs[(ty + 16 * i) * 132 + kd]);
#pragma unroll
            for (int j = 0; j < 4; j++)
                b4[j] = *reinterpret_cast<const float4*>(&Ks[(tx + 16 * j) * 132 + kd]);
#pragma unroll
            for (int i = 0; i < 4; i++)
#pragma unroll
                for (int j = 0; j < 4; j++)
                    acc[i][j] += a4[i].x * b4[j].x + a4[i].y * b4[j].y +
                                 a4[i].z * b4[j].z + a4[i].w * b4[j].w;
        }

        const float sc = 0.088388347648318447f;   // 1/sqrt(128)
        const bool diag = (jb == qi);
#pragma unroll
        for (int i = 0; i < 4; i++)
#pragma unroll
            for (int j = 0; j < 4; j++) {
                float s = acc[i][j] * sc;
                if (diag && (tx + 16 * j) > (ty + 16 * i)) s = -1e30f;
                acc[i][j] = s;
            }

        // online softmax update
#pragma unroll
        for (int i = 0; i < 4; i++) {
            float rm = fmaxf(fmaxf(acc[i][0], acc[i][1]), fmaxf(acc[i][2], acc[i][3]));
#pragma unroll
            for (int off = 8; off >= 1; off >>= 1)
                rm = fmaxf(rm, __shfl_xor_sync(0xffffffffu, rm, off));
            float mn = fmaxf(m_i[i], rm);
            float alpha = __expf(m_i[i] - mn);
            m_i[i] = mn;
            float rs = 0.f;
#pragma unroll
            for (int j = 0; j < 4; j++) {
                float p = __expf(acc[i][j] - mn);
                acc[i][j] = p;
                rs += p;
            }
#pragma unroll
            for (int off = 8; off >= 1; off >>= 1)
                rs += __shfl_xor_sync(0xffffffffu, rs, off);
            l_i[i] = l_i[i] * alpha + rs;
            unsigned long long a2 = pack2(alpha, alpha);
#pragma unroll
            for (int j = 0; j < 4; j++) o2[i][j] = mul2(o2[i][j], a2);
#pragma unroll
            for (int j = 0; j < 4; j++) Ps[(ty + 16 * i) * 68 + tx + 16 * j] = acc[i][j];
        }
        __syncthreads();   // Ps visible; all S reads of Ks done

        // O += P @ V (f32x2 accumulation, contiguous O columns)
#pragma unroll 2
        for (int kk = 0; kk < 64; kk++) {
            float4 v0 = *reinterpret_cast<const float4*>(&Vs[kk * 132 + tx * 8]);
            float4 v1 = *reinterpret_cast<const float4*>(&Vs[kk * 132 + tx * 8 + 4]);
            unsigned long long vb[4];
            vb[0] = pack2(v0.x, v0.y);
            vb[1] = pack2(v0.z, v0.w);
            vb[2] = pack2(v1.x, v1.y);
            vb[3] = pack2(v1.z, v1.w);
#pragma unroll
            for (int i = 0; i < 4; i++) {
                float pav = Ps[(ty + 16 * i) * 68 + kk];
                unsigned long long pa2 = pack2(pav, pav);
#pragma unroll
                for (int j = 0; j < 4; j++) o2[i][j] = fma2(pa2, vb[j], o2[i][j]);
            }
        }
    }

    // epilogue: normalize and store token-major [tok, h*128 + d]
#pragma unroll
    for (int i = 0; i < 4; i++) {
        float inv = 1.0f / l_i[i];
        float2 c0 = unpack2(o2[i][0]);
        float2 c1 = unpack2(o2[i][1]);
        float2 c2 = unpack2(o2[i][2]);
        float2 c3 = unpack2(o2[i][3]);
        size_t base = ((size_t)(b * S_) + qi * 64 + ty + 16 * i) * (NH_ * D_) + h * D_ + tx * 8;
        *reinterpret_cast<float4*>(&ao[base]) =
            make_float4(c0.x * inv, c0.y * inv, c1.x * inv, c1.y * inv);
        *reinterpret_cast<float4*>(&ao[base + 4]) =
            make_float4(c2.x * inv, c2.y * inv, c3.x * inv, c3.y * inv);
    }
}

// ---------------------------------------------------------------------------
// Launch
// inputs: hidden_states, cos, sin, Wq, Wk, Wv, Wo, q_norm_w, k_norm_w
// ---------------------------------------------------------------------------
extern "C" void kernel_launch(void* const* d_in, const int* in_sizes, int n_in,
                              void* d_out, int out_size)
{
    const float* hidden = (const float*)d_in[0];
    const float* cosb   = (const float*)d_in[1];
    const float* sinb   = (const float*)d_in[2];
    const float* Wq     = (const float*)d_in[3];
    const float* Wk     = (const float*)d_in[4];
    const float* Wv     = (const float*)d_in[5];
    const float* Wo     = (const float*)d_in[6];
    const float* qw     = (const float*)d_in[7];
    const float* kw     = (const float*)d_in[8];
    float* out = (float*)d_out;

    float *gq, *gk, *gv, *gao;
    cudaGetSymbolAddress((void**)&gq,  g_q);
    cudaGetSymbolAddress((void**)&gk,  g_k);
    cudaGetSymbolAddress((void**)&gv,  g_v);
    cudaGetSymbolAddress((void**)&gao, g_ao);

    cudaFuncSetAttribute((const void*)attn_kernel,
                         cudaFuncAttributeMaxDynamicSharedMemorySize, ATTN_SMEM);

    dim3 blk(256);
    // QKV projections: [4096,1024] @ W^T
    gemm_nt_128<<<dim3((NH_ * D_) / 128, TOK / 128), blk>>>(hidden, Wq, gq, TOK, NH_ * D_, H_);
    gemm_nt_128<<<dim3((NKV_ * D_) / 128, TOK / 128), blk>>>(hidden, Wk, gk, TOK, NKV_ * D_, H_);
    gemm_nt_128<<<dim3((NKV_ * D_) / 128, TOK / 128), blk>>>(hidden, Wv, gv, TOK, NKV_ * D_, H_);

    // fused RMSNorm + RoPE on q and k (in place)
    rmsnorm_rope_kernel<<<dim3(TOK, NH_ + NKV_), 128>>>(gq, gk, cosb, sinb, qw, kw);

    // causal flash attention
    attn_kernel<<<dim3(S_ / 64, NH_, B_), 256, ATTN_SMEM>>>(gq, gk, gv, gao);

    // output projection: [4096,2048] @ Wo^T -> [4096,1024]
    gemm_nt_128<<<dim3(H_ / 128, TOK / 128), blk>>>(gao, Wo, out, TOK, H_, NH_ * D_);
}

// round 3
// speedup vs baseline: 1.3645x; 1.3645x over previous
#include <cuda_runtime.h>
#include <cstdint>

// ---------------------------------------------------------------------------
// Problem constants (B=2, S=2048, H=1024, NH=16, NKV=8, D=128)
// ---------------------------------------------------------------------------
constexpr int B_   = 2;
constexpr int S_   = 2048;
constexpr int H_   = 1024;
constexpr int NH_  = 16;
constexpr int NKV_ = 8;
constexpr int D_   = 128;
constexpr int TOK  = B_ * S_;            // 4096 tokens

// Scratch (device globals; no allocation allowed)
__device__ float g_q [TOK * NH_  * D_];
__device__ float g_k [TOK * NKV_ * D_];
__device__ float g_v [TOK * NKV_ * D_];
__device__ float g_ao[TOK * NH_  * D_];

#define DEV_INLINE __device__ __forceinline__

// ---------------------------------------------------------------------------
// Packed f32x2 helpers (FFMA2 via PTX) — used by the fp32 attention kernel
// ---------------------------------------------------------------------------
DEV_INLINE unsigned long long pack2(float lo, float hi) {
    unsigned long long r;
    asm("mov.b64 %0, {%1, %2};"
        : "=l"(r) : "r"(__float_as_uint(lo)), "r"(__float_as_uint(hi)));
    return r;
}
DEV_INLINE unsigned long long fma2(unsigned long long a, unsigned long long b,
                                   unsigned long long c) {
    unsigned long long d;
    asm("fma.rn.f32x2 %0, %1, %2, %3;" : "=l"(d) : "l"(a), "l"(b), "l"(c));
    return d;
}
DEV_INLINE unsigned long long mul2(unsigned long long a, unsigned long long b) {
    unsigned long long d;
    asm("mul.rn.f32x2 %0, %1, %2;" : "=l"(d) : "l"(a), "l"(b));
    return d;
}
DEV_INLINE float2 unpack2(unsigned long long v) {
    unsigned int lo, hi;
    asm("mov.b64 {%0, %1}, %2;" : "=r"(lo), "=r"(hi) : "l"(v));
    return make_float2(__uint_as_float(lo), __uint_as_float(hi));
}

// ---------------------------------------------------------------------------
// mma.sync bf16 helpers (baseline sm_80+ PTX — no arch-suffix features)
// ---------------------------------------------------------------------------
DEV_INLINE uint32_t cvt_bf16x2(float hi_elem, float lo_elem) {
    // result.lo16 = bf16(lo_elem), result.hi16 = bf16(hi_elem)
    uint32_t r;
    asm("cvt.rn.bf16x2.f32 %0, %1, %2;" : "=r"(r) : "f"(hi_elem), "f"(lo_elem));
    return r;
}

// split two fp32 (f0 -> low lane, f1 -> high lane) into bf16 hi-pair + lo-pair
DEV_INLINE void split_pair(float f0, float f1, uint32_t& hiw, uint32_t& low) {
    hiw = cvt_bf16x2(f1, f0);
    float h0 = __uint_as_float(hiw << 16);
    float h1 = __uint_as_float(hiw & 0xFFFF0000u);
    low = cvt_bf16x2(f1 - h1, f0 - h0);
}

DEV_INLINE void ldsm_x4(uint32_t* r, uint32_t addr) {
    asm volatile("ldmatrix.sync.aligned.m8n8.x4.shared.b16 {%0,%1,%2,%3}, [%4];"
                 : "=r"(r[0]), "=r"(r[1]), "=r"(r[2]), "=r"(r[3]) : "r"(addr));
}

DEV_INLINE void mma_bf16(float* c, const uint32_t* a, const uint32_t* b) {
    asm volatile(
        "mma.sync.aligned.m16n8k16.row.col.f32.bf16.bf16.f32 "
        "{%0,%1,%2,%3}, {%4,%5,%6,%7}, {%8,%9}, {%0,%1,%2,%3};"
        : "+f"(c[0]), "+f"(c[1]), "+f"(c[2]), "+f"(c[3])
        : "r"(a[0]), "r"(a[1]), "r"(a[2]), "r"(a[3]), "r"(b[0]), "r"(b[1]));
}

// ---------------------------------------------------------------------------
// bf16x3 tensor-core NT GEMM: C[m,n] = sum_k A[m,k]*B[n,k]
// CTA tile 128x128, BK=32, 256 threads (8 warps: 4m x 2n, warp tile 32x64).
// SMEM: per buffer {A_hi, A_lo, B_hi, B_lo}, each 128 rows x 32 bf16,
// row stride 80 B (conflict-free for ldmatrix: banks 20*i mod 32 partition).
// Double buffered. M,N multiples of 128; K multiple of 64.
// 3 products per k-step: Ahi*Bhi + Ahi*Blo + Alo*Bhi  (residual ~2^-18)
// ---------------------------------------------------------------------------
constexpr int GMATB = 10240;           // bytes per matrix tile (128 * 80)
constexpr int GBUFB = 4 * GMATB;       // 40960 per buffer
constexpr int GSMEM = 2 * GBUFB;       // 81920 total

__global__ void __launch_bounds__(256, 1)
gemm_bf16x3(const float* __restrict__ A, const float* __restrict__ Bm,
            float* __restrict__ C, int M, int N, int K)
{
    extern __shared__ char smem[];
    uint32_t sb;
    asm("{ .reg .u64 t; cvta.to.shared.u64 t, %1; cvt.u32.u64 %0, t; }"
        : "=r"(sb) : "l"(smem));

    const int tid  = threadIdx.x;
    const int lane = tid & 31;
    const int wid  = tid >> 5;
    const int wm   = wid & 3;           // warp m index (4)
    const int wn   = wid >> 2;          // warp n index (2)
    const int m0   = blockIdx.y * 128;
    const int n0   = blockIdx.x * 128;

    // global load mapping: each thread owns one row r, one 16-col half
    const int r    = tid >> 1;          // 0..127
    const int half = tid & 1;           // 0 or 1 (cols half*16 .. +15)
    const float* Arow = A  + (size_t)(m0 + r) * K + half * 16;
    const float* Brow = Bm + (size_t)(n0 + r) * K + half * 16;

    float Cacc[2][8][4];
#pragma unroll
    for (int mi = 0; mi < 2; mi++)
#pragma unroll
        for (int nf = 0; nf < 8; nf++)
#pragma unroll
            for (int e = 0; e < 4; e++) Cacc[mi][nf][e] = 0.f;

    float4 ra[4], rb[4];
#pragma unroll
    for (int i = 0; i < 4; i++) {
        ra[i] = *reinterpret_cast<const float4*>(Arow + i * 4);
        rb[i] = *reinterpret_cast<const float4*>(Brow + i * 4);
    }

    // ldmatrix lane addressing pieces (row = lane&15, k-half = lane>>4)
    const uint32_t lrow = (uint32_t)(lane & 15);
    const uint32_t lcol = (uint32_t)(lane >> 4) * 16;   // bytes

    const int NC = K / 32;
    for (int c = 0; c < NC; c++) {
        char* bp = smem + (c & 1) * GBUFB;
        const uint32_t bufs = sb + (c & 1) * GBUFB;

        // ---- split + store this chunk (A then B) ----
        {
            uint32_t hiw[8], low[8];
#pragma unroll
            for (int i = 0; i < 4; i++) {
                split_pair(ra[i].x, ra[i].y, hiw[i * 2],     low[i * 2]);
                split_pair(ra[i].z, ra[i].w, hiw[i * 2 + 1], low[i * 2 + 1]);
            }
            const uint32_t off = (uint32_t)r * 80 + (uint32_t)half * 32;
            *reinterpret_cast<uint4*>(bp + off)              = make_uint4(hiw[0], hiw[1], hiw[2], hiw[3]);
            *reinterpret_cast<uint4*>(bp + off + 16)         = make_uint4(hiw[4], hiw[5], hiw[6], hiw[7]);
            *reinterpret_cast<uint4*>(bp + GMATB + off)      = make_uint4(low[0], low[1], low[2], low[3]);
            *reinterpret_cast<uint4*>(bp + GMATB + off + 16) = make_uint4(low[4], low[5], low[6], low[7]);
#pragma unroll
            for (int i = 0; i < 4; i++) {
                split_pair(rb[i].x, rb[i].y, hiw[i * 2],     low[i * 2]);
                split_pair(rb[i].z, rb[i].w, hiw[i * 2 + 1], low[i * 2 + 1]);
            }
            *reinterpret_cast<uint4*>(bp + 2 * GMATB + off)      = make_uint4(hiw[0], hiw[1], hiw[2], hiw[3]);
            *reinterpret_cast<uint4*>(bp + 2 * GMATB + off + 16) = make_uint4(hiw[4], hiw[5], hiw[6], hiw[7]);
            *reinterpret_cast<uint4*>(bp + 3 * GMATB + off)      = make_uint4(low[0], low[1], low[2], low[3]);
            *reinterpret_cast<uint4*>(bp + 3 * GMATB + off + 16) = make_uint4(low[4], low[5], low[6], low[7]);
        }
        __syncthreads();

        // ---- prefetch next chunk (overlaps with mma) ----
        if (c + 1 < NC) {
            const int k0 = (c + 1) * 32;
#pragma unroll
            for (int i = 0; i < 4; i++) {
                ra[i] = *reinterpret_cast<const float4*>(Arow + k0 + i * 4);
                rb[i] = *reinterpret_cast<const float4*>(Brow + k0 + i * 4);
            }
        }

        // ---- tensor-core compute on this chunk ----
#pragma unroll
        for (int ks = 0; ks < 2; ks++) {
            uint32_t af[2][2][4];   // [sel][mi][4]
            uint32_t bfr[2][8][2];  // [sel][nfrag][2]
#pragma unroll
            for (int sel = 0; sel < 2; sel++) {
#pragma unroll
                for (int mi = 0; mi < 2; mi++) {
                    const uint32_t addr = bufs + (uint32_t)sel * GMATB +
                        ((uint32_t)(wm * 32 + mi * 16) + lrow) * 80 +
                        (uint32_t)ks * 32 + lcol;
                    ldsm_x4(af[sel][mi], addr);
                }
#pragma unroll
                for (int ng = 0; ng < 4; ng++) {
                    uint32_t t[4];
                    const uint32_t addr = bufs + 2 * GMATB + (uint32_t)sel * GMATB +
                        ((uint32_t)(wn * 64 + ng * 16) + lrow) * 80 +
                        (uint32_t)ks * 32 + lcol;
                    ldsm_x4(t, addr);
                    bfr[sel][ng * 2][0]     = t[0];
                    bfr[sel][ng * 2][1]     = t[2];
                    bfr[sel][ng * 2 + 1][0] = t[1];
                    bfr[sel][ng * 2 + 1][1] = t[3];
                }
            }
            // hi*hi
#pragma unroll
            for (int mi = 0; mi < 2; mi++)
#pragma unroll
                for (int nf = 0; nf < 8; nf++)
                    mma_bf16(Cacc[mi][nf], af[0][mi], bfr[0][nf]);
            // hi*lo
#pragma unroll
            for (int mi = 0; mi < 2; mi++)
#pragma unroll
                for (int nf = 0; nf < 8; nf++)
                    mma_bf16(Cacc[mi][nf], af[0][mi], bfr[1][nf]);
            // lo*hi
#pragma unroll
            for (int mi = 0; mi < 2; mi++)
#pragma unroll
                for (int nf = 0; nf < 8; nf++)
                    mma_bf16(Cacc[mi][nf], af[1][mi], bfr[0][nf]);
        }
        __syncthreads();
    }

    // ---- epilogue: write C fragments ----
#pragma unroll
    for (int mi = 0; mi < 2; mi++) {
        const int row = m0 + wm * 32 + mi * 16 + (lane >> 2);
#pragma unroll
        for (int nf = 0; nf < 8; nf++) {
            const int col = n0 + wn * 64 + nf * 8 + (lane & 3) * 2;
            *reinterpret_cast<float2*>(C + (size_t)row * N + col) =
                make_float2(Cacc[mi][nf][0], Cacc[mi][nf][1]);
            *reinterpret_cast<float2*>(C + (size_t)(row + 8) * N + col) =
                make_float2(Cacc[mi][nf][2], Cacc[mi][nf][3]);
        }
    }
}

// ---------------------------------------------------------------------------
// Fused per-head RMSNorm + RoPE, in place on q / k (token-major layouts).
// ---------------------------------------------------------------------------
__global__ void rmsnorm_rope_kernel(float* __restrict__ qbuf, float* __restrict__ kbuf,
                                    const float* __restrict__ cosb,
                                    const float* __restrict__ sinb,
                                    const float* __restrict__ qw,
                                    const float* __restrict__ kw)
{
    const int t  = blockIdx.x;
    const int hh = blockIdx.y;
    const int d  = threadIdx.x;

    float* ptr;
    const float* w;
    if (hh < NH_) { ptr = qbuf + (size_t)t * (NH_ * D_)  + hh * D_;         w = qw; }
    else          { ptr = kbuf + (size_t)t * (NKV_ * D_) + (hh - NH_) * D_; w = kw; }

    const float x  = ptr[d];
    const float xp = ptr[d ^ 64];

    float ss = x * x;
#pragma unroll
    for (int off = 16; off >= 1; off >>= 1) ss += __shfl_xor_sync(0xffffffffu, ss, off);
    __shared__ float red[4];
    if ((d & 31) == 0) red[d >> 5] = ss;
    __syncthreads();

    const float var = (red[0] + red[1] + red[2] + red[3]) * (1.0f / 128.0f);
    const float inv = rsqrtf(var + 1e-6f);

    const float xn  = x  * inv * w[d];
    const float xpn = xp * inv * w[d ^ 64];
    const float c = cosb[(size_t)t * D_ + d];
    const float s = sinb[(size_t)t * D_ + d];
    const float rot = (d < 64) ? -xpn : xpn;

    ptr[d] = xn * c + rot * s;
}

// ---------------------------------------------------------------------------
// Flash attention (fp32, causal, GQA n_rep=2). Unchanged (passed round 0).
// ---------------------------------------------------------------------------
constexpr int ATTN_SMEM = (3 * 64 * 132 + 64 * 68) * 4;

__launch_bounds__(256, 1)
__global__ void attn_kernel(const float* __restrict__ q,
                            const float* __restrict__ k,
                            const float* __restrict__ v,
                            float* __restrict__ ao)
{
    extern __shared__ float sm[];
    float* Qs = sm;
    float* Ks = Qs + 64 * 132;
    float* Vs = Ks + 64 * 132;
    float* Ps = Vs + 64 * 132;

    const int tid = threadIdx.x;
    const int ty = tid >> 4;
    const int tx = tid & 15;
    const int qi = gridDim.x - 1 - blockIdx.x;
    const int h  = blockIdx.y;
    const int b  = blockIdx.z;
    const int kvh = h >> 1;

#pragma unroll
    for (int rep = 0; rep < 8; rep++) {
        int f = tid + rep * 256;
        int row = f >> 5, c4 = f & 31;
        float4 val = *reinterpret_cast<const float4*>(
            q + ((size_t)(b * S_) + qi * 64 + row) * (NH_ * D_) + h * D_ + c4 * 4);
        *reinterpret_cast<float4*>(&Qs[row * 132 + c4 * 4]) = val;
    }

    float m_i[4], l_i[4];
    unsigned long long o2[4][4];
#pragma unroll
    for (int i = 0; i < 4; i++) {
        m_i[i] = -1e30f; l_i[i] = 0.f;
#pragma unroll
        for (int j = 0; j < 4; j++) o2[i][j] = 0ull;
    }

    for (int jb = 0; jb <= qi; jb++) {
        __syncthreads();

#pragma unroll
        for (int rep = 0; rep < 8; rep++) {
            int f = tid + rep * 256;
            int row = f >> 5, c4 = f & 31;
            size_t gidx = ((size_t)(b * S_) + jb * 64 + row) * (NKV_ * D_) + kvh * D_ + c4 * 4;
            *reinterpret_cast<float4*>(&Ks[row * 132 + c4 * 4]) =
                *reinterpret_cast<const float4*>(k + gidx);
            *reinterpret_cast<float4*>(&Vs[row * 132 + c4 * 4]) =
                *reinterpret_cast<const float4*>(v + gidx);
        }
        __syncthreads();

        float acc[4][4];
#pragma unroll
        for (int i = 0; i < 4; i++)
#pragma unroll
            for (int j = 0; j < 4; j++) acc[i][j] = 0.f;

#pragma unroll 4
        for (int kd = 0; kd < D_; kd += 4) {
            float4 a4[4], b4[4];
#pragma unroll
            for (int i = 0; i < 4; i++)
                a4[i] = *reinterpret_cast<const float4*>(&Qs[(ty + 16 * i) * 132 + kd]);
#pragma unroll
            for (int j = 0; j < 4; j++)
                b4[j] = *reinterpret_cast<const float4*>(&Ks[(tx + 16 * j) * 132 + kd]);
#pragma unroll
            for (int i = 0; i < 4; i++)
#pragma unroll
                for (int j = 0; j < 4; j++)
                    acc[i][j] += a4[i].x * b4[j].x + a4[i].y * b4[j].y +
                                 a4[i].z * b4[j].z + a4[i].w * b4[j].w;
        }

        const float sc = 0.088388347648318447f;
        const bool diag = (jb == qi);
#pragma unroll
        for (int i = 0; i < 4; i++)
#pragma unroll
            for (int j = 0; j < 4; j++) {
                float s = acc[i][j] * sc;
                if (diag && (tx + 16 * j) > (ty + 16 * i)) s = -1e30f;
                acc[i][j] = s;
            }

#pragma unroll
        for (int i = 0; i < 4; i++) {
            float rm = fmaxf(fmaxf(acc[i][0], acc[i][1]), fmaxf(acc[i][2], acc[i][3]));
#pragma unroll
            for (int off = 8; off >= 1; off >>= 1)
                rm = fmaxf(rm, __shfl_xor_sync(0xffffffffu, rm, off));
            float mn = fmaxf(m_i[i], rm);
            float alpha = __expf(m_i[i] - mn);
            m_i[i] = mn;
            float rs = 0.f;
#pragma unroll
            for (int j = 0; j < 4; j++) {
                float p = __expf(acc[i][j] - mn);
                acc[i][j] = p;
                rs += p;
            }
#pragma unroll
            for (int off = 8; off >= 1; off >>= 1)
                rs += __shfl_xor_sync(0xffffffffu, rs, off);
            l_i[i] = l_i[i] * alpha + rs;
            unsigned long long a2 = pack2(alpha, alpha);
#pragma unroll
            for (int j = 0; j < 4; j++) o2[i][j] = mul2(o2[i][j], a2);
#pragma unroll
            for (int j = 0; j < 4; j++) Ps[(ty + 16 * i) * 68 + tx + 16 * j] = acc[i][j];
        }
        __syncthreads();

#pragma unroll 2
        for (int kk = 0; kk < 64; kk++) {
            float4 v0 = *reinterpret_cast<const float4*>(&Vs[kk * 132 + tx * 8]);
            float4 v1 = *reinterpret_cast<const float4*>(&Vs[kk * 132 + tx * 8 + 4]);
            unsigned long long vb[4];
            vb[0] = pack2(v0.x, v0.y);
            vb[1] = pack2(v0.z, v0.w);
            vb[2] = pack2(v1.x, v1.y);
            vb[3] = pack2(v1.z, v1.w);
#pragma unroll
            for (int i = 0; i < 4; i++) {
                float pav = Ps[(ty + 16 * i) * 68 + kk];
                unsigned long long pa2 = pack2(pav, pav);
#pragma unroll
                for (int j = 0; j < 4; j++) o2[i][j] = fma2(pa2, vb[j], o2[i][j]);
            }
        }
    }

#pragma unroll
    for (int i = 0; i < 4; i++) {
        float inv = 1.0f / l_i[i];
        float2 c0 = unpack2(o2[i][0]);
        float2 c1 = unpack2(o2[i][1]);
        float2 c2 = unpack2(o2[i][2]);
        float2 c3 = unpack2(o2[i][3]);
        size_t base = ((size_t)(b * S_) + qi * 64 + ty + 16 * i) * (NH_ * D_) + h * D_ + tx * 8;
        *reinterpret_cast<float4*>(&ao[base]) =
            make_float4(c0.x * inv, c0.y * inv, c1.x * inv, c1.y * inv);
        *reinterpret_cast<float4*>(&ao[base + 4]) =
            make_float4(c2.x * inv, c2.y * inv, c3.x * inv, c3.y * inv);
    }
}

// ---------------------------------------------------------------------------
// Launch
// ---------------------------------------------------------------------------
extern "C" void kernel_launch(void* const* d_in, const int* in_sizes, int n_in,
                              void* d_out, int out_size)
{
    const float* hidden = (const float*)d_in[0];
    const float* cosb   = (const float*)d_in[1];
    const float* sinb   = (const float*)d_in[2];
    const float* Wq     = (const float*)d_in[3];
    const float* Wk     = (const float*)d_in[4];
    const float* Wv     = (const float*)d_in[5];
    const float* Wo     = (const float*)d_in[6];
    const float* qw     = (const float*)d_in[7];
    const float* kw     = (const float*)d_in[8];
    float* out = (float*)d_out;

    float *gq, *gk, *gv, *gao;
    cudaGetSymbolAddress((void**)&gq,  g_q);
    cudaGetSymbolAddress((void**)&gk,  g_k);
    cudaGetSymbolAddress((void**)&gv,  g_v);
    cudaGetSymbolAddress((void**)&gao, g_ao);

    cudaFuncSetAttribute((const void*)attn_kernel,
                         cudaFuncAttributeMaxDynamicSharedMemorySize, ATTN_SMEM);
    cudaFuncSetAttribute((const void*)gemm_bf16x3,
                         cudaFuncAttributeMaxDynamicSharedMemorySize, GSMEM);

    // QKV projections on tensor cores (bf16x3 via mma.sync)
    gemm_bf16x3<<<dim3((NH_ * D_) / 128, TOK / 128), 256, GSMEM>>>(
        hidden, Wq, gq, TOK, NH_ * D_, H_);
    gemm_bf16x3<<<dim3((NKV_ * D_) / 128, TOK / 128), 256, GSMEM>>>(
        hidden, Wk, gk, TOK, NKV_ * D_, H_);
    gemm_bf16x3<<<dim3((NKV_ * D_) / 128, TOK / 128), 256, GSMEM>>>(
        hidden, Wv, gv, TOK, NKV_ * D_, H_);

    rmsnorm_rope_kernel<<<dim3(TOK, NH_ + NKV_), 128>>>(gq, gk, cosb, sinb, qw, kw);

    attn_kernel<<<dim3(S_ / 64, NH_, B_), 256, ATTN_SMEM>>>(gq, gk, gv, gao);

    // output projection on tensor cores
    gemm_bf16x3<<<dim3(H_ / 128, TOK / 128), 256, GSMEM>>>(
        gao, Wo, out, TOK, H_, NH_ * D_);
}

// round 4
// speedup vs baseline: 2.5281x; 1.8528x over previous
#include <cuda_runtime.h>
#include <cuda_bf16.h>
#include <cstdint>

// ---------------------------------------------------------------------------
// Problem constants (B=2, S=2048, H=1024, NH=16, NKV=8, D=128)
// ---------------------------------------------------------------------------
constexpr int B_   = 2;
constexpr int S_   = 2048;
constexpr int H_   = 1024;
constexpr int NH_  = 16;
constexpr int NKV_ = 8;
constexpr int D_   = 128;
constexpr int TOK  = B_ * S_;            // 4096 tokens

// Scratch (device globals; no allocation allowed)
__device__ float g_q [TOK * NH_  * D_];
__device__ float g_k [TOK * NKV_ * D_];
__device__ float g_v [TOK * NKV_ * D_];
__device__ float g_ao[TOK * NH_  * D_];
// bf16 hi/lo split buffers for attention operands
__device__ __nv_bfloat16 g_qh[TOK * NH_  * D_];
__device__ __nv_bfloat16 g_ql[TOK * NH_  * D_];
__device__ __nv_bfloat16 g_kh[TOK * NKV_ * D_];
__device__ __nv_bfloat16 g_kl[TOK * NKV_ * D_];
__device__ __nv_bfloat16 g_vh[TOK * NKV_ * D_];
__device__ __nv_bfloat16 g_vl[TOK * NKV_ * D_];

#define DEV_INLINE __device__ __forceinline__

// ---------------------------------------------------------------------------
// mma.sync bf16 helpers (baseline sm_80+ PTX — no arch-suffix features)
// ---------------------------------------------------------------------------
DEV_INLINE uint32_t cvt_bf16x2(float hi_elem, float lo_elem) {
    uint32_t r;
    asm("cvt.rn.bf16x2.f32 %0, %1, %2;" : "=r"(r) : "f"(hi_elem), "f"(lo_elem));
    return r;
}
// split two fp32 (f0 -> low lane, f1 -> high lane) into bf16 hi-pair + lo-pair
DEV_INLINE void split_pair(float f0, float f1, uint32_t& hiw, uint32_t& low) {
    hiw = cvt_bf16x2(f1, f0);
    float h0 = __uint_as_float(hiw << 16);
    float h1 = __uint_as_float(hiw & 0xFFFF0000u);
    low = cvt_bf16x2(f1 - h1, f0 - h0);
}
DEV_INLINE void ldsm_x4(uint32_t* r, uint32_t addr) {
    asm volatile("ldmatrix.sync.aligned.m8n8.x4.shared.b16 {%0,%1,%2,%3}, [%4];"
                 : "=r"(r[0]), "=r"(r[1]), "=r"(r[2]), "=r"(r[3]) : "r"(addr));
}
DEV_INLINE void ldsm_x4_trans(uint32_t* r, uint32_t addr) {
    asm volatile("ldmatrix.sync.aligned.m8n8.x4.trans.shared.b16 {%0,%1,%2,%3}, [%4];"
                 : "=r"(r[0]), "=r"(r[1]), "=r"(r[2]), "=r"(r[3]) : "r"(addr));
}
DEV_INLINE void mma_bf16(float* c, const uint32_t* a, const uint32_t* b) {
    asm volatile(
        "mma.sync.aligned.m16n8k16.row.col.f32.bf16.bf16.f32 "
        "{%0,%1,%2,%3}, {%4,%5,%6,%7}, {%8,%9}, {%0,%1,%2,%3};"
        : "+f"(c[0]), "+f"(c[1]), "+f"(c[2]), "+f"(c[3])
        : "r"(a[0]), "r"(a[1]), "r"(a[2]), "r"(a[3]), "r"(b[0]), "r"(b[1]));
}
DEV_INLINE uint32_t smem_u32(const void* p) {
    uint32_t a;
    asm("{ .reg .u64 t; cvta.to.shared.u64 t, %1; cvt.u32.u64 %0, t; }"
        : "=r"(a) : "l"(p));
    return a;
}
// cp.async (sm_80 baseline feature)
DEV_INLINE void cp16(uint32_t dst, const void* src) {
    asm volatile("cp.async.cg.shared.global [%0], [%1], 16;"
                 :: "r"(dst), "l"(src) : "memory");
}
DEV_INLINE void cp_commit() { asm volatile("cp.async.commit_group;" ::: "memory"); }
DEV_INLINE void cp_wait1()  { asm volatile("cp.async.wait_group 1;" ::: "memory"); }
DEV_INLINE void cp_wait0()  { asm volatile("cp.async.wait_group 0;" ::: "memory"); }

// ---------------------------------------------------------------------------
// bf16x3 tensor-core NT GEMM (unchanged from round 3, validated)
// ---------------------------------------------------------------------------
constexpr int GMATB = 10240;           // bytes per matrix tile (128 * 80)
constexpr int GBUFB = 4 * GMATB;       // 40960 per buffer
constexpr int GSMEM = 2 * GBUFB;       // 81920 total

__global__ void __launch_bounds__(256, 1)
gemm_bf16x3(const float* __restrict__ A, const float* __restrict__ Bm,
            float* __restrict__ C, int M, int N, int K)
{
    extern __shared__ char smem[];
    const uint32_t sb = smem_u32(smem);

    const int tid  = threadIdx.x;
    const int lane = tid & 31;
    const int wid  = tid >> 5;
    const int wm   = wid & 3;
    const int wn   = wid >> 2;
    const int m0   = blockIdx.y * 128;
    const int n0   = blockIdx.x * 128;

    const int r    = tid >> 1;
    const int half = tid & 1;
    const float* Arow = A  + (size_t)(m0 + r) * K + half * 16;
    const float* Brow = Bm + (size_t)(n0 + r) * K + half * 16;

    float Cacc[2][8][4];
#pragma unroll
    for (int mi = 0; mi < 2; mi++)
#pragma unroll
        for (int nf = 0; nf < 8; nf++)
#pragma unroll
            for (int e = 0; e < 4; e++) Cacc[mi][nf][e] = 0.f;

    float4 ra[4], rb[4];
#pragma unroll
    for (int i = 0; i < 4; i++) {
        ra[i] = *reinterpret_cast<const float4*>(Arow + i * 4);
        rb[i] = *reinterpret_cast<const float4*>(Brow + i * 4);
    }

    const uint32_t lrow = (uint32_t)(lane & 15);
    const uint32_t lcol = (uint32_t)(lane >> 4) * 16;

    const int NC = K / 32;
    for (int c = 0; c < NC; c++) {
        char* bp = smem + (c & 1) * GBUFB;
        const uint32_t bufs = sb + (c & 1) * GBUFB;

        {
            uint32_t hiw[8], low[8];
#pragma unroll
            for (int i = 0; i < 4; i++) {
                split_pair(ra[i].x, ra[i].y, hiw[i * 2],     low[i * 2]);
                split_pair(ra[i].z, ra[i].w, hiw[i * 2 + 1], low[i * 2 + 1]);
            }
            const uint32_t off = (uint32_t)r * 80 + (uint32_t)half * 32;
            *reinterpret_cast<uint4*>(bp + off)              = make_uint4(hiw[0], hiw[1], hiw[2], hiw[3]);
            *reinterpret_cast<uint4*>(bp + off + 16)         = make_uint4(hiw[4], hiw[5], hiw[6], hiw[7]);
            *reinterpret_cast<uint4*>(bp + GMATB + off)      = make_uint4(low[0], low[1], low[2], low[3]);
            *reinterpret_cast<uint4*>(bp + GMATB + off + 16) = make_uint4(low[4], low[5], low[6], low[7]);
#pragma unroll
            for (int i = 0; i < 4; i++) {
                split_pair(rb[i].x, rb[i].y, hiw[i * 2],     low[i * 2]);
                split_pair(rb[i].z, rb[i].w, hiw[i * 2 + 1], low[i * 2 + 1]);
            }
            *reinterpret_cast<uint4*>(bp + 2 * GMATB + off)      = make_uint4(hiw[0], hiw[1], hiw[2], hiw[3]);
            *reinterpret_cast<uint4*>(bp + 2 * GMATB + off + 16) = make_uint4(hiw[4], hiw[5], hiw[6], hiw[7]);
            *reinterpret_cast<uint4*>(bp + 3 * GMATB + off)      = make_uint4(low[0], low[1], low[2], low[3]);
            *reinterpret_cast<uint4*>(bp + 3 * GMATB + off + 16) = make_uint4(low[4], low[5], low[6], low[7]);
        }
        __syncthreads();

        if (c + 1 < NC) {
            const int k0 = (c + 1) * 32;
#pragma unroll
            for (int i = 0; i < 4; i++) {
                ra[i] = *reinterpret_cast<const float4*>(Arow + k0 + i * 4);
                rb[i] = *reinterpret_cast<const float4*>(Brow + k0 + i * 4);
            }
        }

#pragma unroll
        for (int ks = 0; ks < 2; ks++) {
            uint32_t af[2][2][4];
            uint32_t bfr[2][8][2];
#pragma unroll
            for (int sel = 0; sel < 2; sel++) {
#pragma unroll
                for (int mi = 0; mi < 2; mi++) {
                    const uint32_t addr = bufs + (uint32_t)sel * GMATB +
                        ((uint32_t)(wm * 32 + mi * 16) + lrow) * 80 +
                        (uint32_t)ks * 32 + lcol;
                    ldsm_x4(af[sel][mi], addr);
                }
#pragma unroll
                for (int ng = 0; ng < 4; ng++) {
                    uint32_t t[4];
                    const uint32_t addr = bufs + 2 * GMATB + (uint32_t)sel * GMATB +
                        ((uint32_t)(wn * 64 + ng * 16) + lrow) * 80 +
                        (uint32_t)ks * 32 + lcol;
                    ldsm_x4(t, addr);
                    bfr[sel][ng * 2][0]     = t[0];
                    bfr[sel][ng * 2][1]     = t[2];
                    bfr[sel][ng * 2 + 1][0] = t[1];
                    bfr[sel][ng * 2 + 1][1] = t[3];
                }
            }
#pragma unroll
            for (int mi = 0; mi < 2; mi++)
#pragma unroll
                for (int nf = 0; nf < 8; nf++)
                    mma_bf16(Cacc[mi][nf], af[0][mi], bfr[0][nf]);
#pragma unroll
            for (int mi = 0; mi < 2; mi++)
#pragma unroll
                for (int nf = 0; nf < 8; nf++)
                    mma_bf16(Cacc[mi][nf], af[0][mi], bfr[1][nf]);
#pragma unroll
            for (int mi = 0; mi < 2; mi++)
#pragma unroll
                for (int nf = 0; nf < 8; nf++)
                    mma_bf16(Cacc[mi][nf], af[1][mi], bfr[0][nf]);
        }
        __syncthreads();
    }

#pragma unroll
    for (int mi = 0; mi < 2; mi++) {
        const int row = m0 + wm * 32 + mi * 16 + (lane >> 2);
#pragma unroll
        for (int nf = 0; nf < 8; nf++) {
            const int col = n0 + wn * 64 + nf * 8 + (lane & 3) * 2;
            *reinterpret_cast<float2*>(C + (size_t)row * N + col) =
                make_float2(Cacc[mi][nf][0], Cacc[mi][nf][1]);
            *reinterpret_cast<float2*>(C + (size_t)(row + 8) * N + col) =
                make_float2(Cacc[mi][nf][2], Cacc[mi][nf][3]);
        }
    }
}

// ---------------------------------------------------------------------------
// Fused RMSNorm + RoPE + bf16 hi/lo split (q, k), and split-only (v).
// grid: (TOK, NH + NKV + NKV), block 128.
// ---------------------------------------------------------------------------
__global__ void rmsnorm_rope_split_kernel(
    const float* __restrict__ qbuf, const float* __restrict__ kbuf,
    const float* __restrict__ vbuf,
    const float* __restrict__ cosb, const float* __restrict__ sinb,
    const float* __restrict__ qw,   const float* __restrict__ kw,
    __nv_bfloat16* __restrict__ qh, __nv_bfloat16* __restrict__ ql,
    __nv_bfloat16* __restrict__ kh, __nv_bfloat16* __restrict__ kl,
    __nv_bfloat16* __restrict__ vh, __nv_bfloat16* __restrict__ vl)
{
    const int t  = blockIdx.x;
    const int hh = blockIdx.y;
    const int d  = threadIdx.x;

    if (hh >= NH_ + NKV_) {                 // v: split only
        const int hv = hh - NH_ - NKV_;
        const size_t idx = (size_t)t * (NKV_ * D_) + hv * D_ + d;
        const float y = vbuf[idx];
        const __nv_bfloat16 hb = __float2bfloat16(y);
        vh[idx] = hb;
        vl[idx] = __float2bfloat16(y - __bfloat162float(hb));
        return;
    }

    const float* ptr;
    const float* w;
    __nv_bfloat16 *oh, *ol;
    size_t idx;
    if (hh < NH_) {
        idx = (size_t)t * (NH_ * D_) + hh * D_ + d;
        ptr = qbuf; w = qw; oh = qh; ol = ql;
    } else {
        idx = (size_t)t * (NKV_ * D_) + (hh - NH_) * D_ + d;
        ptr = kbuf; w = kw; oh = kh; ol = kl;
    }

    const size_t rowbase = idx - d;
    const float x  = ptr[rowbase + d];
    const float xp = ptr[rowbase + (d ^ 64)];

    float ss = x * x;
#pragma unroll
    for (int off = 16; off >= 1; off >>= 1) ss += __shfl_xor_sync(0xffffffffu, ss, off);
    __shared__ float red[4];
    if ((d & 31) == 0) red[d >> 5] = ss;
    __syncthreads();

    const float var = (red[0] + red[1] + red[2] + red[3]) * (1.0f / 128.0f);
    const float inv = rsqrtf(var + 1e-6f);

    const float xn  = x  * inv * w[d];
    const float xpn = xp * inv * w[d ^ 64];
    const float c = cosb[(size_t)t * D_ + d];
    const float s = sinb[(size_t)t * D_ + d];
    const float rot = (d < 64) ? -xpn : xpn;
    const float y = xn * c + rot * s;

    const __nv_bfloat16 hb = __float2bfloat16(y);
    oh[idx] = hb;
    ol[idx] = __float2bfloat16(y - __bfloat162float(hb));
}

// ---------------------------------------------------------------------------
// Tensor-core flash attention (bf16x3, causal, GQA n_rep=2).
// BQ=128, BKV=64, D=128. 256 threads = 8 warps, warp w -> q rows w*16..+15.
// SMEM: Qhi,Qlo (128x272B each) + double-buffered {Khi,Klo,Vhi,Vlo} (64x272B each)
// ---------------------------------------------------------------------------
constexpr int AQ_BYTES  = 128 * 272;                 // 34816
constexpr int AKV_BYTES = 64 * 272;                  // 17408
constexpr int ABUF0     = 2 * AQ_BYTES;              // 69632
constexpr int ABUFSZ    = 4 * AKV_BYTES;             // 69632
constexpr int ATTN_SMEM = ABUF0 + 2 * ABUFSZ;        // 208896

__global__ void __launch_bounds__(256, 1)
attn_bf16_kernel(const __nv_bfloat16* __restrict__ qh, const __nv_bfloat16* __restrict__ ql,
                 const __nv_bfloat16* __restrict__ kh, const __nv_bfloat16* __restrict__ kl,
                 const __nv_bfloat16* __restrict__ vh, const __nv_bfloat16* __restrict__ vl,
                 float* __restrict__ ao)
{
    extern __shared__ char smem[];
    const uint32_t sb = smem_u32(smem);

    const int tid  = threadIdx.x;
    const int lane = tid & 31;
    const int w    = tid >> 5;                       // 0..7
    const int qi   = gridDim.x - 1 - blockIdx.x;     // heavy blocks first
    const int h    = blockIdx.y;
    const int b    = blockIdx.z;
    const int kvh  = h >> 1;                         // GQA

    // ---- prologue: Q hi/lo + kv(0) in async group 0 ----
#pragma unroll
    for (int i = 0; i < 8; i++) {
        const int idx = tid + i * 256;               // 0..2047
        const int row = idx >> 4, ch = idx & 15;
        const size_t g = ((size_t)(b * S_) + qi * 128 + row) * (NH_ * D_) + h * D_ + ch * 8;
        cp16(sb + row * 272 + ch * 16,            qh + g);
        cp16(sb + AQ_BYTES + row * 272 + ch * 16, ql + g);
    }
    {
        const uint32_t buf = sb + ABUF0;             // buffer 0
#pragma unroll
        for (int i = 0; i < 4; i++) {
            const int idx = tid + i * 256;           // 0..1023
            const int row = idx >> 4, ch = idx & 15;
            const size_t g = ((size_t)(b * S_) + row) * (NKV_ * D_) + kvh * D_ + ch * 8;
            const uint32_t so = buf + row * 272 + ch * 16;
            cp16(so,                 kh + g);
            cp16(so + AKV_BYTES,     kl + g);
            cp16(so + 2 * AKV_BYTES, vh + g);
            cp16(so + 3 * AKV_BYTES, vl + g);
        }
    }
    cp_commit();

    float oacc[16][4];
#pragma unroll
    for (int i = 0; i < 16; i++)
#pragma unroll
        for (int e = 0; e < 4; e++) oacc[i][e] = 0.f;
    float m_i[2] = {-1e30f, -1e30f};
    float l_i[2] = {0.f, 0.f};

    const uint32_t lrow16 = (uint32_t)(lane & 15);
    const uint32_t lhalf  = (uint32_t)(lane >> 4) * 16;
    const int jmax = 2 * qi + 1;

    for (int jb = 0; jb <= jmax; jb++) {
        // issue next kv tile, then wait for current one
        if (jb < jmax) {
            const uint32_t buf = sb + ABUF0 + ((jb + 1) & 1) * ABUFSZ;
#pragma unroll
            for (int i = 0; i < 4; i++) {
                const int idx = tid + i * 256;
                const int row = idx >> 4, ch = idx & 15;
                const size_t g = ((size_t)(b * S_) + (jb + 1) * 64 + row) * (NKV_ * D_) +
                                 kvh * D_ + ch * 8;
                const uint32_t so = buf + row * 272 + ch * 16;
                cp16(so,                 kh + g);
                cp16(so + AKV_BYTES,     kl + g);
                cp16(so + 2 * AKV_BYTES, vh + g);
                cp16(so + 3 * AKV_BYTES, vl + g);
            }
            cp_commit();
            cp_wait1();
        } else {
            cp_wait0();
        }
        __syncthreads();

        const uint32_t kb = sb + ABUF0 + (jb & 1) * ABUFSZ;
        const bool skip = (jb * 64) > (qi * 128 + w * 16 + 15);   // fully masked warp tile

        if (!skip) {
            // ---- S = Q K^T (bf16x3) ----
            float sacc[8][4];
#pragma unroll
            for (int i = 0; i < 8; i++)
#pragma unroll
                for (int e = 0; e < 4; e++) sacc[i][e] = 0.f;

            const uint32_t qbase = sb + ((uint32_t)(w * 16) + lrow16) * 272 + lhalf;
#pragma unroll
            for (int ks = 0; ks < 8; ks++) {
                uint32_t ahi[4], alo[4];
                ldsm_x4(ahi, qbase + ks * 32);
                ldsm_x4(alo, qbase + AQ_BYTES + ks * 32);
#pragma unroll
                for (int ng = 0; ng < 4; ng++) {
                    uint32_t t[4], u[4];
                    const uint32_t ka = kb + ((uint32_t)(ng * 16) + lrow16) * 272 + ks * 32 + lhalf;
                    ldsm_x4(t, ka);
                    ldsm_x4(u, ka + AKV_BYTES);
                    uint32_t bh0[2] = {t[0], t[2]}, bh1[2] = {t[1], t[3]};
                    uint32_t bl0[2] = {u[0], u[2]}, bl1[2] = {u[1], u[3]};
                    mma_bf16(sacc[ng * 2],     ahi, bh0);
                    mma_bf16(sacc[ng * 2 + 1], ahi, bh1);
                    mma_bf16(sacc[ng * 2],     ahi, bl0);
                    mma_bf16(sacc[ng * 2 + 1], ahi, bl1);
                    mma_bf16(sacc[ng * 2],     alo, bh0);
                    mma_bf16(sacc[ng * 2 + 1], alo, bh1);
                }
            }

            // ---- scale + causal mask ----
            const float sc = 0.088388347648318447f;  // 1/sqrt(128)
            const bool domask = (jb * 64 + 63) > (qi * 128 + w * 16);
#pragma unroll
            for (int nf = 0; nf < 8; nf++)
#pragma unroll
                for (int e = 0; e < 4; e++) {
                    float s = sacc[nf][e] * sc;
                    if (domask) {
                        const int col = jb * 64 + nf * 8 + ((lane & 3) << 1) + (e & 1);
                        const int row = qi * 128 + w * 16 + (lane >> 2) + ((e >> 1) << 3);
                        if (col > row) s = -1e30f;
                    }
                    sacc[nf][e] = s;
                }

            // ---- online softmax (rows r and r+8 per thread) ----
#pragma unroll
            for (int r2 = 0; r2 < 2; r2++) {
                float mx = -1e30f;
#pragma unroll
                for (int nf = 0; nf < 8; nf++)
                    mx = fmaxf(mx, fmaxf(sacc[nf][2 * r2], sacc[nf][2 * r2 + 1]));
                mx = fmaxf(mx, __shfl_xor_sync(0xffffffffu, mx, 1));
                mx = fmaxf(mx, __shfl_xor_sync(0xffffffffu, mx, 2));
                const float mn = fmaxf(m_i[r2], mx);
                const float alpha = __expf(m_i[r2] - mn);
                m_i[r2] = mn;
                float rs = 0.f;
#pragma unroll
                for (int nf = 0; nf < 8; nf++) {
                    float p0 = __expf(sacc[nf][2 * r2]     - mn);
                    float p1 = __expf(sacc[nf][2 * r2 + 1] - mn);
                    sacc[nf][2 * r2]     = p0;
                    sacc[nf][2 * r2 + 1] = p1;
                    rs += p0 + p1;
                }
                rs += __shfl_xor_sync(0xffffffffu, rs, 1);
                rs += __shfl_xor_sync(0xffffffffu, rs, 2);
                l_i[r2] = l_i[r2] * alpha + rs;
#pragma unroll
                for (int ndf = 0; ndf < 16; ndf++) {
                    oacc[ndf][2 * r2]     *= alpha;
                    oacc[ndf][2 * r2 + 1] *= alpha;
                }
            }

            // ---- O += P V (bf16x3); P C-frags -> A-frags in registers ----
#pragma unroll
            for (int kk = 0; kk < 4; kk++) {
                uint32_t phi[4], plo[4];
                split_pair(sacc[2 * kk][0],     sacc[2 * kk][1],     phi[0], plo[0]);
                split_pair(sacc[2 * kk][2],     sacc[2 * kk][3],     phi[1], plo[1]);
                split_pair(sacc[2 * kk + 1][0], sacc[2 * kk + 1][1], phi[2], plo[2]);
                split_pair(sacc[2 * kk + 1][2], sacc[2 * kk + 1][3], phi[3], plo[3]);
#pragma unroll
                for (int ndg = 0; ndg < 8; ndg++) {
                    uint32_t t[4], u[4];
                    const uint32_t va = kb + 2 * AKV_BYTES +
                        ((uint32_t)(kk * 16) + lrow16) * 272 + ndg * 32 + lhalf;
                    ldsm_x4_trans(t, va);
                    ldsm_x4_trans(u, va + AKV_BYTES);
                    uint32_t bh0[2] = {t[0], t[1]}, bh1[2] = {t[2], t[3]};
                    uint32_t bl0[2] = {u[0], u[1]}, bl1[2] = {u[2], u[3]};
                    mma_bf16(oacc[ndg * 2],     phi, bh0);
                    mma_bf16(oacc[ndg * 2 + 1], phi, bh1);
                    mma_bf16(oacc[ndg * 2],     phi, bl0);
                    mma_bf16(oacc[ndg * 2 + 1], phi, bl1);
                    mma_bf16(oacc[ndg * 2],     plo, bh0);
                    mma_bf16(oacc[ndg * 2 + 1], plo, bh1);
                }
            }
        }
        __syncthreads();   // all reads of buf done before its next overwrite
    }

    // ---- epilogue: normalize and store fp32 token-major ----
    const float i0 = 1.0f / l_i[0];
    const float i1 = 1.0f / l_i[1];
    const int row0 = qi * 128 + w * 16 + (lane >> 2);
    const size_t base0 = ((size_t)(b * S_) + row0) * (NH_ * D_) + h * D_ + (lane & 3) * 2;
    const size_t base1 = base0 + (size_t)8 * (NH_ * D_);
#pragma unroll
    for (int ndf = 0; ndf < 16; ndf++) {
        *reinterpret_cast<float2*>(ao + base0 + ndf * 8) =
            make_float2(oacc[ndf][0] * i0, oacc[ndf][1] * i0);
        *reinterpret_cast<float2*>(ao + base1 + ndf * 8) =
            make_float2(oacc[ndf][2] * i1, oacc[ndf][3] * i1);
    }
}

// ---------------------------------------------------------------------------
// Launch
// ---------------------------------------------------------------------------
extern "C" void kernel_launch(void* const* d_in, const int* in_sizes, int n_in,
                              void* d_out, int out_size)
{
    const float* hidden = (const float*)d_in[0];
    const float* cosb   = (const float*)d_in[1];
    const float* sinb   = (const float*)d_in[2];
    const float* Wq     = (const float*)d_in[3];
    const float* Wk     = (const float*)d_in[4];
    const float* Wv     = (const float*)d_in[5];
    const float* Wo     = (const float*)d_in[6];
    const float* qw     = (const float*)d_in[7];
    const float* kw     = (const float*)d_in[8];
    float* out = (float*)d_out;

    float *gq, *gk, *gv, *gao;
    cudaGetSymbolAddress((void**)&gq,  g_q);
    cudaGetSymbolAddress((void**)&gk,  g_k);
    cudaGetSymbolAddress((void**)&gv,  g_v);
    cudaGetSymbolAddress((void**)&gao, g_ao);
    __nv_bfloat16 *qh, *ql, *kh, *kl, *vh, *vl;
    cudaGetSymbolAddress((void**)&qh, g_qh);
    cudaGetSymbolAddress((void**)&ql, g_ql);
    cudaGetSymbolAddress((void**)&kh, g_kh);
    cudaGetSymbolAddress((void**)&kl, g_kl);
    cudaGetSymbolAddress((void**)&vh, g_vh);
    cudaGetSymbolAddress((void**)&vl, g_vl);

    cudaFuncSetAttribute((const void*)gemm_bf16x3,
                         cudaFuncAttributeMaxDynamicSharedMemorySize, GSMEM);
    cudaFuncSetAttribute((const void*)attn_bf16_kernel,
                         cudaFuncAttributeMaxDynamicSharedMemorySize, ATTN_SMEM);

    // QKV projections on tensor cores (bf16x3 via mma.sync)
    gemm_bf16x3<<<dim3((NH_ * D_) / 128, TOK / 128), 256, GSMEM>>>(
        hidden, Wq, gq, TOK, NH_ * D_, H_);
    gemm_bf16x3<<<dim3((NKV_ * D_) / 128, TOK / 128), 256, GSMEM>>>(
        hidden, Wk, gk, TOK, NKV_ * D_, H_);
    gemm_bf16x3<<<dim3((NKV_ * D_) / 128, TOK / 128), 256, GSMEM>>>(
        hidden, Wv, gv, TOK, NKV_ * D_, H_);

    // fused RMSNorm + RoPE + bf16 hi/lo split (q,k) and split (v)
    rmsnorm_rope_split_kernel<<<dim3(TOK, NH_ + 2 * NKV_), 128>>>(
        gq, gk, gv, cosb, sinb, qw, kw, qh, ql, kh, kl, vh, vl);

    // tensor-core causal flash attention
    attn_bf16_kernel<<<dim3(S_ / 128, NH_, B_), 256, ATTN_SMEM>>>(
        qh, ql, kh, kl, vh, vl, gao);

    // output projection on tensor cores
    gemm_bf16x3<<<dim3(H_ / 128, TOK / 128), 256, GSMEM>>>(
        gao, Wo, out, TOK, H_, NH_ * D_);
}